// round 1
// baseline (speedup 1.0000x reference)
#include <cuda_runtime.h>

// Problem constants
#define Bn 4
#define Tn 2048
#define Cn 512
#define Hn 8
#define Dn 64
__device__ __constant__ float kScale = 0.04419417382415922f; // 512^-0.5

// Scratch (device globals; no allocation allowed)
__device__ float g_q[Bn*Hn*Tn*Dn];    // [b][h][t][d]
__device__ float g_k[Bn*Hn*Tn*Dn];
__device__ float g_v[Bn*Hn*Tn*Dn];
__device__ float g_att[Bn*Tn*Cn];     // [b][t][h*D+d]

// ---------------------------------------------------------------------------
// Kernel 1: fused QKV projection.
// grid = (128 m-tiles, 24): blockIdx.y -> {which of q/k/v} x {head}
// Each block: 64x64 output tile of one head's projection, K=512.
// ---------------------------------------------------------------------------
__global__ __launch_bounds__(256) void qkv_kernel(
    const float* __restrict__ x,
    const float* __restrict__ Wq,
    const float* __restrict__ Wk,
    const float* __restrict__ Wv)
{
    __shared__ float As[64*33];  // [m][kk] kk=32 chunk
    __shared__ float Bs[32*65];  // [kk][d]

    const int m0   = blockIdx.x * 64;
    const int wsel = blockIdx.y >> 3;
    const int h    = blockIdx.y & 7;
    const float* W = (wsel == 0 ? Wq : (wsel == 1 ? Wk : Wv)) + h * Cn * Dn;
    float* out     = (wsel == 0 ? g_q : (wsel == 1 ? g_k : g_v));

    const int tid = threadIdx.x;
    const int tx = tid & 15, ty = tid >> 4;
    const int row0 = ty * 4, col0 = tx * 4;

    float acc[4][4] = {};

    for (int c0 = 0; c0 < Cn; c0 += 32) {
        for (int idx = tid; idx < 64*32; idx += 256) {
            int kk = idx & 31, mm = idx >> 5;
            As[mm*33 + kk] = x[(m0 + mm) * Cn + c0 + kk];
        }
        for (int idx = tid; idx < 32*64; idx += 256) {
            int d = idx & 63, kk = idx >> 6;
            Bs[kk*65 + d] = W[(c0 + kk) * Dn + d];
        }
        __syncthreads();
        #pragma unroll 8
        for (int kk = 0; kk < 32; kk++) {
            float a[4], b[4];
            #pragma unroll
            for (int i = 0; i < 4; i++) a[i] = As[(row0 + i)*33 + kk];
            #pragma unroll
            for (int j = 0; j < 4; j++) b[j] = Bs[kk*65 + col0 + j];
            #pragma unroll
            for (int i = 0; i < 4; i++)
                #pragma unroll
                for (int j = 0; j < 4; j++)
                    acc[i][j] += a[i] * b[j];
        }
        __syncthreads();
    }

    #pragma unroll
    for (int i = 0; i < 4; i++) {
        int m = m0 + row0 + i;
        int b = m >> 11;        // m / T
        int t = m & 2047;       // m % T
        float4 v4 = make_float4(acc[i][0], acc[i][1], acc[i][2], acc[i][3]);
        *reinterpret_cast<float4*>(&out[((b * Hn + h) * Tn + t) * Dn + col0]) = v4;
    }
}

// ---------------------------------------------------------------------------
// Kernel 2: flash attention with Transformer-XL rel-shift.
// grid = (B*H, 32 query-blocks). blockIdx.y reversed so heaviest blocks first.
// Per key tile: S1 = Q K^T fused with R_A = Q RelA^T in one K-loop, then
// diagonal gather; second Rel half only for off-diagonal tiles; online
// softmax; P V accumulate.
// ---------------------------------------------------------------------------
__global__ __launch_bounds__(256, 2) void attn_kernel(const float* __restrict__ rel)
{
    extern __shared__ float sm[];
    float* Qs  = sm;             // [64][65]  (rows t, cols d)
    float* Ks  = Qs  + 64*65;    // [64][65]  (rows s, cols d)
    float* RAs = Ks  + 64*65;    // [64][65]  (rows jj 0..63, cols d)
    float* RBs = RAs + 64*65;    // [64][65]  (rows jj 64..127, cols d)
    float* Vs  = RBs + 64*65;    // [64][65]  (rows s, cols d)
    float* Ps  = Vs  + 64*65;    // [64][65]  scratch: R tile / P tile (rows t)

    const int tid = threadIdx.x;
    const int tx = tid & 15, ty = tid >> 4;
    const int row0 = ty * 4, col0 = tx * 4;

    const int bh = blockIdx.x;
    const int h  = bh & (Hn - 1);
    const int b  = bh >> 3;
    const int t0 = (int)(gridDim.y - 1 - blockIdx.y) * 64;

    const float* qg   = g_q + (size_t)bh * Tn * Dn;
    const float* kg   = g_k + (size_t)bh * Tn * Dn;
    const float* vg   = g_v + (size_t)bh * Tn * Dn;
    const float* relh = rel + (size_t)h * Tn * Dn;

    for (int idx = tid; idx < 64*64; idx += 256) {
        int d = idx & 63, r = idx >> 6;
        Qs[r*65 + d] = qg[(t0 + r) * Dn + d];
    }

    float O[4][4] = {};
    float mrow[4] = {-1e30f, -1e30f, -1e30f, -1e30f};
    float lrow[4] = {};

    for (int s0 = 0; s0 <= t0; s0 += 64) {
        const bool diag = (s0 == t0);
        __syncthreads();  // previous tile's compute done with smem (also covers Q load)

        for (int idx = tid; idx < 64*64; idx += 256) {
            int d = idx & 63, r = idx >> 6;
            Ks[r*65 + d] = kg[(s0 + r) * Dn + d];
            Vs[r*65 + d] = vg[(s0 + r) * Dn + d];
        }
        const int jbase = s0 - t0 + Tn - 64;  // >= 0 always; jbase+63 <= T-1 always
        for (int idx = tid; idx < 64*64; idx += 256) {
            int d = idx & 63, r = idx >> 6;
            RAs[r*65 + d] = relh[(jbase + r) * Dn + d];
        }
        if (!diag) {
            // off-diagonal: s0 <= t0-64  =>  jbase+64+63 <= T-1, no clamp needed
            for (int idx = tid; idx < 64*64; idx += 256) {
                int d = idx & 63, r = idx >> 6;
                RBs[r*65 + d] = relh[(jbase + 64 + r) * Dn + d];
            }
        }
        __syncthreads();

        // --- S1 = Q K^T fused with R_A = Q RelA^T ---
        float S[4][4] = {};
        {
            float R[4][4] = {};
            #pragma unroll 8
            for (int kk = 0; kk < 64; kk++) {
                float a[4], bk[4], br[4];
                #pragma unroll
                for (int i = 0; i < 4; i++) a[i]  = Qs[(row0 + i)*65 + kk];
                #pragma unroll
                for (int j = 0; j < 4; j++) bk[j] = Ks[(col0 + j)*65 + kk];
                #pragma unroll
                for (int j = 0; j < 4; j++) br[j] = RAs[(col0 + j)*65 + kk];
                #pragma unroll
                for (int i = 0; i < 4; i++)
                    #pragma unroll
                    for (int j = 0; j < 4; j++) {
                        S[i][j] += a[i] * bk[j];
                        R[i][j] += a[i] * br[j];
                    }
            }
            #pragma unroll
            for (int i = 0; i < 4; i++)
                #pragma unroll
                for (int j = 0; j < 4; j++)
                    Ps[(row0 + i)*65 + col0 + j] = R[i][j];
        }
        __syncthreads();
        // gather BD from R_A: jj = sl - tl + 63 in [0,63]  <=>  sl <= tl
        #pragma unroll
        for (int i = 0; i < 4; i++)
            #pragma unroll
            for (int j = 0; j < 4; j++) {
                int jj = (col0 + j) - (row0 + i) + 63;
                if (jj < 64) S[i][j] += Ps[(row0 + i)*65 + jj];
            }
        __syncthreads();

        if (!diag) {
            float R[4][4] = {};
            #pragma unroll 8
            for (int kk = 0; kk < 64; kk++) {
                float a[4], br[4];
                #pragma unroll
                for (int i = 0; i < 4; i++) a[i]  = Qs[(row0 + i)*65 + kk];
                #pragma unroll
                for (int j = 0; j < 4; j++) br[j] = RBs[(col0 + j)*65 + kk];
                #pragma unroll
                for (int i = 0; i < 4; i++)
                    #pragma unroll
                    for (int j = 0; j < 4; j++)
                        R[i][j] += a[i] * br[j];
            }
            #pragma unroll
            for (int i = 0; i < 4; i++)
                #pragma unroll
                for (int j = 0; j < 4; j++)
                    Ps[(row0 + i)*65 + col0 + j] = R[i][j];
            __syncthreads();
            #pragma unroll
            for (int i = 0; i < 4; i++)
                #pragma unroll
                for (int j = 0; j < 4; j++) {
                    int jj = (col0 + j) - (row0 + i) + 63;
                    if (jj >= 64) S[i][j] += Ps[(row0 + i)*65 + jj - 64];
                }
            __syncthreads();
        }

        // --- rel-shift wrap corner: only tile (0,0), rows t<5, cols t+1<s<6 ---
        if (t0 == 0 && s0 == 0) {
            #pragma unroll
            for (int i = 0; i < 4; i++)
                #pragma unroll
                for (int j = 0; j < 4; j++) {
                    int t = row0 + i, s = col0 + j;
                    if (s > t + 1 && s < 6) {
                        float bd = 0.f;
                        for (int d = 0; d < 64; d++)
                            bd += Qs[(t + 1)*65 + d] * relh[(s - t - 2) * Dn + d];
                        S[i][j] += bd;  // gathered BD there is 0 (s==t+1 case stays 0)
                    }
                }
        }

        // --- mask + scale + online softmax ---
        float pm[4];
        #pragma unroll
        for (int i = 0; i < 4; i++) {
            int t = t0 + row0 + i;
            float rm = -1e30f;
            #pragma unroll
            for (int j = 0; j < 4; j++) {
                int s = s0 + col0 + j;
                float val = (s <= t || s < 6) ? S[i][j] * kScale : -1e30f;
                S[i][j] = val;
                rm = fmaxf(rm, val);
            }
            rm = fmaxf(rm, __shfl_xor_sync(0xffffffffu, rm, 1));
            rm = fmaxf(rm, __shfl_xor_sync(0xffffffffu, rm, 2));
            rm = fmaxf(rm, __shfl_xor_sync(0xffffffffu, rm, 4));
            rm = fmaxf(rm, __shfl_xor_sync(0xffffffffu, rm, 8));
            pm[i] = rm;
        }
        #pragma unroll
        for (int i = 0; i < 4; i++) {
            float mnew  = fmaxf(mrow[i], pm[i]);
            float alpha = __expf(mrow[i] - mnew);
            mrow[i] = mnew;
            float rs = 0.f;
            #pragma unroll
            for (int j = 0; j < 4; j++) {
                float p = __expf(S[i][j] - mnew);
                S[i][j] = p;
                rs += p;
            }
            rs += __shfl_xor_sync(0xffffffffu, rs, 1);
            rs += __shfl_xor_sync(0xffffffffu, rs, 2);
            rs += __shfl_xor_sync(0xffffffffu, rs, 4);
            rs += __shfl_xor_sync(0xffffffffu, rs, 8);
            lrow[i] = lrow[i] * alpha + rs;
            #pragma unroll
            for (int j = 0; j < 4; j++) O[i][j] *= alpha;
        }

        // --- P -> smem, then O += P V ---
        #pragma unroll
        for (int i = 0; i < 4; i++)
            #pragma unroll
            for (int j = 0; j < 4; j++)
                Ps[(row0 + i)*65 + col0 + j] = S[i][j];
        __syncthreads();
        #pragma unroll 8
        for (int kk = 0; kk < 64; kk++) {
            float a[4], bv[4];
            #pragma unroll
            for (int i = 0; i < 4; i++) a[i]  = Ps[(row0 + i)*65 + kk];
            #pragma unroll
            for (int j = 0; j < 4; j++) bv[j] = Vs[kk*65 + col0 + j];
            #pragma unroll
            for (int i = 0; i < 4; i++)
                #pragma unroll
                for (int j = 0; j < 4; j++)
                    O[i][j] += a[i] * bv[j];
        }
    }

    #pragma unroll
    for (int i = 0; i < 4; i++) {
        int t = t0 + row0 + i;
        float inv = 1.0f / lrow[i];
        float4 o4 = make_float4(O[i][0]*inv, O[i][1]*inv, O[i][2]*inv, O[i][3]*inv);
        *reinterpret_cast<float4*>(&g_att[((size_t)b * Tn + t) * Cn + h * Dn + col0]) = o4;
    }
}

// ---------------------------------------------------------------------------
// Kernel 3: output projection + bias. grid = (128, 8), 64x64 tiles, K=512.
// ---------------------------------------------------------------------------
__global__ __launch_bounds__(256) void proj_kernel(
    const float* __restrict__ Wp,
    const float* __restrict__ bp,
    float* __restrict__ out)
{
    __shared__ float As[64*33];
    __shared__ float Bs[32*65];

    const int m0 = blockIdx.x * 64;
    const int n0 = blockIdx.y * 64;
    const int tid = threadIdx.x;
    const int tx = tid & 15, ty = tid >> 4;
    const int row0 = ty * 4, col0 = tx * 4;

    float acc[4][4] = {};

    for (int c0 = 0; c0 < Cn; c0 += 32) {
        for (int idx = tid; idx < 64*32; idx += 256) {
            int kk = idx & 31, mm = idx >> 5;
            As[mm*33 + kk] = g_att[(size_t)(m0 + mm) * Cn + c0 + kk];
        }
        for (int idx = tid; idx < 32*64; idx += 256) {
            int d = idx & 63, kk = idx >> 6;
            Bs[kk*65 + d] = Wp[(size_t)(c0 + kk) * Cn + n0 + d];
        }
        __syncthreads();
        #pragma unroll 8
        for (int kk = 0; kk < 32; kk++) {
            float a[4], b[4];
            #pragma unroll
            for (int i = 0; i < 4; i++) a[i] = As[(row0 + i)*33 + kk];
            #pragma unroll
            for (int j = 0; j < 4; j++) b[j] = Bs[kk*65 + col0 + j];
            #pragma unroll
            for (int i = 0; i < 4; i++)
                #pragma unroll
                for (int j = 0; j < 4; j++)
                    acc[i][j] += a[i] * b[j];
        }
        __syncthreads();
    }

    #pragma unroll
    for (int i = 0; i < 4; i++) {
        int m = m0 + row0 + i;
        float4 o4;
        o4.x = acc[i][0] + bp[n0 + col0 + 0];
        o4.y = acc[i][1] + bp[n0 + col0 + 1];
        o4.z = acc[i][2] + bp[n0 + col0 + 2];
        o4.w = acc[i][3] + bp[n0 + col0 + 3];
        *reinterpret_cast<float4*>(&out[(size_t)m * Cn + n0 + col0]) = o4;
    }
}

// ---------------------------------------------------------------------------
extern "C" void kernel_launch(void* const* d_in, const int* in_sizes, int n_in,
                              void* d_out, int out_size)
{
    const float* x   = (const float*)d_in[0];
    const float* Wq  = (const float*)d_in[1];
    const float* Wk  = (const float*)d_in[2];
    const float* Wv  = (const float*)d_in[3];
    const float* rel = (const float*)d_in[4];
    const float* Wp  = (const float*)d_in[5];
    const float* bp  = (const float*)d_in[6];
    float* out = (float*)d_out;

    const int attn_smem = 6 * 64 * 65 * (int)sizeof(float);  // 99840 B
    cudaFuncSetAttribute(attn_kernel, cudaFuncAttributeMaxDynamicSharedMemorySize,
                         attn_smem);

    dim3 blk(256);
    qkv_kernel<<<dim3(128, 24), blk>>>(x, Wq, Wk, Wv);
    attn_kernel<<<dim3(Bn * Hn, Tn / 64), blk, attn_smem>>>(rel);
    proj_kernel<<<dim3(128, 8), blk>>>(Wp, bp, out);
}

// round 3
// speedup vs baseline: 1.5031x; 1.5031x over previous
#include <cuda_runtime.h>
#include <cuda_bf16.h>
#include <cstdint>

// Problem constants
#define Bn 4
#define Tn 2048
#define Cn 512
#define Hn 8
#define Dn 64
__device__ __constant__ float kScale = 0.04419417382415922f; // 512^-0.5

// Scratch (device globals; no allocation allowed)
__device__ __align__(16) float g_q[Bn*Hn*Tn*Dn];    // [b][h][t][d]
__device__ __align__(16) float g_k[Bn*Hn*Tn*Dn];
__device__ __align__(16) float g_v[Bn*Hn*Tn*Dn];
__device__ __align__(16) float g_att[Bn*Tn*Cn];     // [b][t][h*D+d]

// ---------------------------------------------------------------------------
// mma.sync helpers (sm_80+ features; compile on plain sm_100 target)
// ---------------------------------------------------------------------------
__device__ __forceinline__ uint32_t smem_u32(const void* p) {
    uint32_t a;
    asm("{ .reg .u64 t; cvta.to.shared.u64 t, %1; cvt.u32.u64 %0, t; }"
        : "=r"(a) : "l"(p));
    return a;
}

__device__ __forceinline__ void ldmx4(uint32_t* r, uint32_t addr) {
    asm volatile("ldmatrix.sync.aligned.m8n8.x4.shared.b16 {%0,%1,%2,%3}, [%4];"
                 : "=r"(r[0]), "=r"(r[1]), "=r"(r[2]), "=r"(r[3]) : "r"(addr));
}

__device__ __forceinline__ void mma16816(float* c, const uint32_t* a,
                                         uint32_t b0, uint32_t b1) {
    asm volatile(
        "mma.sync.aligned.m16n8k16.row.col.f32.bf16.bf16.f32 "
        "{%0,%1,%2,%3}, {%4,%5,%6,%7}, {%8,%9}, {%0,%1,%2,%3};"
        : "+f"(c[0]), "+f"(c[1]), "+f"(c[2]), "+f"(c[3])
        : "r"(a[0]), "r"(a[1]), "r"(a[2]), "r"(a[3]), "r"(b0), "r"(b1));
}

// Split fp32 pair into bf16 hi/lo pairs (packed bf16x2 each).
__device__ __forceinline__ void split2(float x0, float x1, uint32_t& hi2, uint32_t& lo2) {
    asm("cvt.rn.bf16x2.f32 %0, %1, %2;" : "=r"(hi2) : "f"(x1), "f"(x0));
    float h0 = __uint_as_float(hi2 << 16);
    float h1 = __uint_as_float(hi2 & 0xFFFF0000u);
    float l0 = x0 - h0, l1 = x1 - h1;
    asm("cvt.rn.bf16x2.f32 %0, %1, %2;" : "=r"(lo2) : "f"(l1), "f"(l0));
}

// Smem tile geometry: bf16 rows padded to 72 elems = 144B (16B-aligned,
// 144/16 = 9 -> ldmatrix 8-row groups hit distinct 16B phases: conflict-free).
#define LDA 144
#define OFF_AH 0
#define OFF_AL 18432
#define OFF_BH 36864
#define OFF_BL 46080
#define GEMM_SMEM 55296

// ---------------------------------------------------------------------------
// Kernel 1: fused QKV projection on mma.sync (split-bf16, 3 MMAs / product).
// grid = (64 m-tiles of 128, 24 = {q,k,v} x head), 256 threads (8 warps x m16).
// D[128x64] = X[128x512] * W[512x64].
// ---------------------------------------------------------------------------
__global__ __launch_bounds__(256) void qkv_mm(
    const float* __restrict__ x,
    const float* __restrict__ Wq,
    const float* __restrict__ Wk,
    const float* __restrict__ Wv)
{
    extern __shared__ char smc[];
    const uint32_t smb = smem_u32(smc);
    const int tid = threadIdx.x;
    const int wm  = tid >> 5;       // warp id = m-subtile
    const int lane = tid & 31;

    const int m0   = blockIdx.x * 128;
    const int wsel = blockIdx.y >> 3;
    const int h    = blockIdx.y & 7;
    const float* W = (wsel == 0 ? Wq : (wsel == 1 ? Wk : Wv)) + (size_t)h * Cn * Dn;
    float* out     = (wsel == 0 ? g_q : (wsel == 1 ? g_k : g_v));

    float c[8][4] = {};

    const int lr = lane & 15;
    const int lc = (lane >> 4) << 3;

    for (int kb = 0; kb < 8; kb++) {
        const int c0 = kb * 64;
        // A tile: 128x64 fp32 -> bf16 hi/lo
        #pragma unroll
        for (int i = 0; i < 4; i++) {
            int u = tid + i * 256;              // 1024 units of 8 cols
            int row = u >> 3, g = u & 7;
            const float4* p = reinterpret_cast<const float4*>(
                x + (size_t)(m0 + row) * Cn + c0 + g * 8);
            float4 a0 = p[0], a1 = p[1];
            uint4 hi, lo;
            split2(a0.x, a0.y, hi.x, lo.x);
            split2(a0.z, a0.w, hi.y, lo.y);
            split2(a1.x, a1.y, hi.z, lo.z);
            split2(a1.z, a1.w, hi.w, lo.w);
            uint32_t off = (uint32_t)(row * LDA + g * 16);
            *reinterpret_cast<uint4*>(smc + OFF_AH + off) = hi;
            *reinterpret_cast<uint4*>(smc + OFF_AL + off) = lo;
        }
        // B tile: W[c0+kk][d] -> Bs[d][kk]  (transpose)
        #pragma unroll
        for (int i = 0; i < 16; i++) {
            int idx = tid + i * 256;
            int d = idx & 63, kk = idx >> 6;
            float w = W[(size_t)(c0 + kk) * Dn + d];
            __nv_bfloat16 hb = __float2bfloat16(w);
            __nv_bfloat16 lb = __float2bfloat16(w - __bfloat162float(hb));
            uint32_t off = (uint32_t)(d * LDA + kk * 2);
            *reinterpret_cast<__nv_bfloat16*>(smc + OFF_BH + off) = hb;
            *reinterpret_cast<__nv_bfloat16*>(smc + OFF_BL + off) = lb;
        }
        __syncthreads();

        #pragma unroll
        for (int ks = 0; ks < 4; ks++) {
            const int k0 = ks * 16;
            uint32_t a_hi[4], a_lo[4];
            uint32_t aoff = (uint32_t)((wm * 16 + lr) * LDA + (k0 + lc) * 2);
            ldmx4(a_hi, smb + OFF_AH + aoff);
            ldmx4(a_lo, smb + OFF_AL + aoff);
            #pragma unroll
            for (int ng = 0; ng < 4; ng++) {
                uint32_t bh[4], bl[4];
                uint32_t boff = (uint32_t)((ng * 16 + lr) * LDA + (k0 + lc) * 2);
                ldmx4(bh, smb + OFF_BH + boff);
                ldmx4(bl, smb + OFF_BL + boff);
                mma16816(c[2*ng],   a_hi, bh[0], bh[2]);
                mma16816(c[2*ng],   a_hi, bl[0], bl[2]);
                mma16816(c[2*ng],   a_lo, bh[0], bh[2]);
                mma16816(c[2*ng+1], a_hi, bh[1], bh[3]);
                mma16816(c[2*ng+1], a_hi, bl[1], bl[3]);
                mma16816(c[2*ng+1], a_lo, bh[1], bh[3]);
            }
        }
        __syncthreads();
    }

    // Epilogue: c-frag (m16n8): lane gid=lane>>2 rows {gid, gid+8}, cols 2(lane&3).
    const int gid = lane >> 2, qc = (lane & 3) * 2;
    #pragma unroll
    for (int rr = 0; rr < 2; rr++) {
        int m = m0 + wm * 16 + gid + rr * 8;
        int b = m >> 11, t = m & 2047;
        float* op = out + (((size_t)(b * Hn + h)) * Tn + t) * Dn;
        #pragma unroll
        for (int j = 0; j < 8; j++) {
            float2 v2 = make_float2(c[j][rr*2], c[j][rr*2 + 1]);
            *reinterpret_cast<float2*>(op + j * 8 + qc) = v2;
        }
    }
}

// ---------------------------------------------------------------------------
// Kernel 3: output projection + bias on mma.sync (split-bf16).
// grid = (64 m-tiles of 128, 8 n-tiles of 64), 256 threads.
// ---------------------------------------------------------------------------
__global__ __launch_bounds__(256) void proj_mm(
    const float* __restrict__ Wp,
    const float* __restrict__ bp,
    float* __restrict__ outp)
{
    extern __shared__ char smc[];
    const uint32_t smb = smem_u32(smc);
    const int tid = threadIdx.x;
    const int wm  = tid >> 5;
    const int lane = tid & 31;

    const int m0 = blockIdx.x * 128;
    const int n0 = blockIdx.y * 64;

    float c[8][4] = {};

    const int lr = lane & 15;
    const int lc = (lane >> 4) << 3;

    for (int kb = 0; kb < 8; kb++) {
        const int c0 = kb * 64;
        #pragma unroll
        for (int i = 0; i < 4; i++) {
            int u = tid + i * 256;
            int row = u >> 3, g = u & 7;
            const float4* p = reinterpret_cast<const float4*>(
                g_att + (size_t)(m0 + row) * Cn + c0 + g * 8);
            float4 a0 = p[0], a1 = p[1];
            uint4 hi, lo;
            split2(a0.x, a0.y, hi.x, lo.x);
            split2(a0.z, a0.w, hi.y, lo.y);
            split2(a1.x, a1.y, hi.z, lo.z);
            split2(a1.z, a1.w, hi.w, lo.w);
            uint32_t off = (uint32_t)(row * LDA + g * 16);
            *reinterpret_cast<uint4*>(smc + OFF_AH + off) = hi;
            *reinterpret_cast<uint4*>(smc + OFF_AL + off) = lo;
        }
        #pragma unroll
        for (int i = 0; i < 16; i++) {
            int idx = tid + i * 256;
            int d = idx & 63, kk = idx >> 6;
            float w = Wp[(size_t)(c0 + kk) * Cn + n0 + d];
            __nv_bfloat16 hb = __float2bfloat16(w);
            __nv_bfloat16 lb = __float2bfloat16(w - __bfloat162float(hb));
            uint32_t off = (uint32_t)(d * LDA + kk * 2);
            *reinterpret_cast<__nv_bfloat16*>(smc + OFF_BH + off) = hb;
            *reinterpret_cast<__nv_bfloat16*>(smc + OFF_BL + off) = lb;
        }
        __syncthreads();

        #pragma unroll
        for (int ks = 0; ks < 4; ks++) {
            const int k0 = ks * 16;
            uint32_t a_hi[4], a_lo[4];
            uint32_t aoff = (uint32_t)((wm * 16 + lr) * LDA + (k0 + lc) * 2);
            ldmx4(a_hi, smb + OFF_AH + aoff);
            ldmx4(a_lo, smb + OFF_AL + aoff);
            #pragma unroll
            for (int ng = 0; ng < 4; ng++) {
                uint32_t bh[4], bl[4];
                uint32_t boff = (uint32_t)((ng * 16 + lr) * LDA + (k0 + lc) * 2);
                ldmx4(bh, smb + OFF_BH + boff);
                ldmx4(bl, smb + OFF_BL + boff);
                mma16816(c[2*ng],   a_hi, bh[0], bh[2]);
                mma16816(c[2*ng],   a_hi, bl[0], bl[2]);
                mma16816(c[2*ng],   a_lo, bh[0], bh[2]);
                mma16816(c[2*ng+1], a_hi, bh[1], bh[3]);
                mma16816(c[2*ng+1], a_hi, bl[1], bl[3]);
                mma16816(c[2*ng+1], a_lo, bh[1], bh[3]);
            }
        }
        __syncthreads();
    }

    const int gid = lane >> 2, qc = (lane & 3) * 2;
    #pragma unroll
    for (int rr = 0; rr < 2; rr++) {
        int m = m0 + wm * 16 + gid + rr * 8;
        float* op = outp + (size_t)m * Cn + n0;
        #pragma unroll
        for (int j = 0; j < 8; j++) {
            float2 bv = *reinterpret_cast<const float2*>(bp + n0 + j * 8 + qc);
            float2 v2 = make_float2(c[j][rr*2] + bv.x, c[j][rr*2 + 1] + bv.y);
            *reinterpret_cast<float2*>(op + j * 8 + qc) = v2;
        }
    }
}

// ---------------------------------------------------------------------------
// Kernel 2: flash attention with Transformer-XL rel-shift (fp32 FFMA).
// R-reuse: the upper rel half-tile of key-tile s0 equals the lower half of
// tile s0+64, so only ONE Q*Rel^T 64x64 GEMM per tile (plus one preload).
// ---------------------------------------------------------------------------
__global__ __launch_bounds__(256, 2) void attn_kernel(const float* __restrict__ rel)
{
    extern __shared__ float sm[];
    float* Qs = sm;             // [64][65]
    float* Ks = Qs + 64*65;
    float* Vs = Ks + 64*65;
    float* Ws = Vs + 64*65;     // rel tile, then P tile (aliased)
    float* R0 = Ws + 64*65;
    float* R1 = R0 + 64*65;

    const int tid = threadIdx.x;
    const int tx = tid & 15, ty = tid >> 4;
    const int row0 = ty * 4, col0 = tx * 4;

    const int bh = blockIdx.x;
    const int h  = bh & (Hn - 1);
    const int b  = bh >> 3;
    const int t0 = (int)(gridDim.y - 1 - blockIdx.y) * 64;

    const float* qg   = g_q + (size_t)bh * Tn * Dn;
    const float* kg   = g_k + (size_t)bh * Tn * Dn;
    const float* vg   = g_v + (size_t)bh * Tn * Dn;
    const float* relh = rel + (size_t)h * Tn * Dn;

    // Load Q and the first rel half-window (rows jbase(0) .. +63)
    const int jbase0 = Tn - 64 - t0;
    for (int idx = tid; idx < 64*64; idx += 256) {
        int d = idx & 63, r = idx >> 6;
        Qs[r*65 + d] = qg[(t0 + r) * Dn + d];
        Ws[r*65 + d] = relh[(size_t)(jbase0 + r) * Dn + d];
    }
    __syncthreads();

    float* Rprev = R0;
    float* Rnew  = R1;

    // Preload: Rprev = Q * RelWin0^T
    {
        float R[4][4] = {};
        #pragma unroll 8
        for (int kk = 0; kk < 64; kk++) {
            float a[4], br[4];
            #pragma unroll
            for (int i = 0; i < 4; i++) a[i]  = Qs[(row0 + i)*65 + kk];
            #pragma unroll
            for (int j = 0; j < 4; j++) br[j] = Ws[(col0 + j)*65 + kk];
            #pragma unroll
            for (int i = 0; i < 4; i++)
                #pragma unroll
                for (int j = 0; j < 4; j++)
                    R[i][j] += a[i] * br[j];
        }
        #pragma unroll
        for (int i = 0; i < 4; i++)
            #pragma unroll
            for (int j = 0; j < 4; j++)
                Rprev[(row0 + i)*65 + col0 + j] = R[i][j];
    }
    __syncthreads();

    float O[4][4] = {};
    float mrow[4] = {-1e30f, -1e30f, -1e30f, -1e30f};
    float lrow[4] = {};

    for (int s0 = 0; s0 <= t0; s0 += 64) {
        const bool diag = (s0 == t0);

        for (int idx = tid; idx < 64*64; idx += 256) {
            int d = idx & 63, r = idx >> 6;
            Ks[r*65 + d] = kg[(s0 + r) * Dn + d];
            Vs[r*65 + d] = vg[(s0 + r) * Dn + d];
        }
        if (!diag) {
            const int jb = s0 - t0 + Tn;   // = jbase + 64
            for (int idx = tid; idx < 64*64; idx += 256) {
                int d = idx & 63, r = idx >> 6;
                Ws[r*65 + d] = relh[(size_t)(jb + r) * Dn + d];
            }
        }
        __syncthreads();

        // S = Q K^T, fused (off-diag) with Rnew = Q RelB^T
        float S[4][4] = {};
        if (!diag) {
            float R[4][4] = {};
            #pragma unroll 8
            for (int kk = 0; kk < 64; kk++) {
                float a[4], bk[4], br[4];
                #pragma unroll
                for (int i = 0; i < 4; i++) a[i]  = Qs[(row0 + i)*65 + kk];
                #pragma unroll
                for (int j = 0; j < 4; j++) bk[j] = Ks[(col0 + j)*65 + kk];
                #pragma unroll
                for (int j = 0; j < 4; j++) br[j] = Ws[(col0 + j)*65 + kk];
                #pragma unroll
                for (int i = 0; i < 4; i++)
                    #pragma unroll
                    for (int j = 0; j < 4; j++) {
                        S[i][j] += a[i] * bk[j];
                        R[i][j] += a[i] * br[j];
                    }
            }
            #pragma unroll
            for (int i = 0; i < 4; i++)
                #pragma unroll
                for (int j = 0; j < 4; j++)
                    Rnew[(row0 + i)*65 + col0 + j] = R[i][j];
        } else {
            #pragma unroll 8
            for (int kk = 0; kk < 64; kk++) {
                float a[4], bk[4];
                #pragma unroll
                for (int i = 0; i < 4; i++) a[i]  = Qs[(row0 + i)*65 + kk];
                #pragma unroll
                for (int j = 0; j < 4; j++) bk[j] = Ks[(col0 + j)*65 + kk];
                #pragma unroll
                for (int i = 0; i < 4; i++)
                    #pragma unroll
                    for (int j = 0; j < 4; j++)
                        S[i][j] += a[i] * bk[j];
            }
        }
        __syncthreads();

        // Gather BD: jj = sl - tl + 63 in [0,126]; low half from Rprev,
        // high half from Rnew (off-diag only; diag never needs jj >= 64).
        #pragma unroll
        for (int i = 0; i < 4; i++)
            #pragma unroll
            for (int j = 0; j < 4; j++) {
                int jj = (col0 + j) - (row0 + i) + 63;
                if (jj < 64) S[i][j] += Rprev[(row0 + i)*65 + jj];
                else if (!diag) S[i][j] += Rnew[(row0 + i)*65 + jj - 64];
            }

        // rel-shift wrap corner: only tile (0,0), rows t<5, cols t+1<s<6
        if (t0 == 0 && s0 == 0) {
            #pragma unroll
            for (int i = 0; i < 4; i++)
                #pragma unroll
                for (int j = 0; j < 4; j++) {
                    int t = row0 + i, s = col0 + j;
                    if (s > t + 1 && s < 6) {
                        float bd = 0.f;
                        for (int d = 0; d < 64; d++)
                            bd += Qs[(t + 1)*65 + d] * relh[(size_t)(s - t - 2) * Dn + d];
                        S[i][j] += bd;
                    }
                }
        }

        // mask + scale + online softmax
        float pm[4];
        #pragma unroll
        for (int i = 0; i < 4; i++) {
            int t = t0 + row0 + i;
            float rm = -1e30f;
            #pragma unroll
            for (int j = 0; j < 4; j++) {
                int s = s0 + col0 + j;
                float val = (s <= t || s < 6) ? S[i][j] * kScale : -1e30f;
                S[i][j] = val;
                rm = fmaxf(rm, val);
            }
            rm = fmaxf(rm, __shfl_xor_sync(0xffffffffu, rm, 1));
            rm = fmaxf(rm, __shfl_xor_sync(0xffffffffu, rm, 2));
            rm = fmaxf(rm, __shfl_xor_sync(0xffffffffu, rm, 4));
            rm = fmaxf(rm, __shfl_xor_sync(0xffffffffu, rm, 8));
            pm[i] = rm;
        }
        #pragma unroll
        for (int i = 0; i < 4; i++) {
            float mnew  = fmaxf(mrow[i], pm[i]);
            float alpha = __expf(mrow[i] - mnew);
            mrow[i] = mnew;
            float rs = 0.f;
            #pragma unroll
            for (int j = 0; j < 4; j++) {
                float p = __expf(S[i][j] - mnew);
                S[i][j] = p;
                rs += p;
            }
            rs += __shfl_xor_sync(0xffffffffu, rs, 1);
            rs += __shfl_xor_sync(0xffffffffu, rs, 2);
            rs += __shfl_xor_sync(0xffffffffu, rs, 4);
            rs += __shfl_xor_sync(0xffffffffu, rs, 8);
            lrow[i] = lrow[i] * alpha + rs;
            #pragma unroll
            for (int j = 0; j < 4; j++) O[i][j] *= alpha;
        }

        // P -> smem (aliases rel buffer, already consumed), then O += P V
        #pragma unroll
        for (int i = 0; i < 4; i++)
            #pragma unroll
            for (int j = 0; j < 4; j++)
                Ws[(row0 + i)*65 + col0 + j] = S[i][j];
        __syncthreads();
        #pragma unroll 8
        for (int kk = 0; kk < 64; kk++) {
            float a[4], bv[4];
            #pragma unroll
            for (int i = 0; i < 4; i++) a[i]  = Ws[(row0 + i)*65 + kk];
            #pragma unroll
            for (int j = 0; j < 4; j++) bv[j] = Vs[kk*65 + col0 + j];
            #pragma unroll
            for (int i = 0; i < 4; i++)
                #pragma unroll
                for (int j = 0; j < 4; j++)
                    O[i][j] += a[i] * bv[j];
        }
        if (!diag) { float* tp = Rprev; Rprev = Rnew; Rnew = tp; }
        __syncthreads();
    }

    #pragma unroll
    for (int i = 0; i < 4; i++) {
        int t = t0 + row0 + i;
        float inv = 1.0f / lrow[i];
        float4 o4 = make_float4(O[i][0]*inv, O[i][1]*inv, O[i][2]*inv, O[i][3]*inv);
        *reinterpret_cast<float4*>(&g_att[((size_t)b * Tn + t) * Cn + h * Dn + col0]) = o4;
    }
}

// ---------------------------------------------------------------------------
extern "C" void kernel_launch(void* const* d_in, const int* in_sizes, int n_in,
                              void* d_out, int out_size)
{
    const float* x   = (const float*)d_in[0];
    const float* Wq  = (const float*)d_in[1];
    const float* Wk  = (const float*)d_in[2];
    const float* Wv  = (const float*)d_in[3];
    const float* rel = (const float*)d_in[4];
    const float* Wp  = (const float*)d_in[5];
    const float* bp  = (const float*)d_in[6];
    float* out = (float*)d_out;

    const int attn_smem = 6 * 64 * 65 * (int)sizeof(float);  // 99840

    cudaFuncSetAttribute(qkv_mm,  cudaFuncAttributeMaxDynamicSharedMemorySize, GEMM_SMEM);
    cudaFuncSetAttribute(proj_mm, cudaFuncAttributeMaxDynamicSharedMemorySize, GEMM_SMEM);
    cudaFuncSetAttribute(attn_kernel, cudaFuncAttributeMaxDynamicSharedMemorySize, attn_smem);

    qkv_mm<<<dim3(64, 24), 256, GEMM_SMEM>>>(x, Wq, Wk, Wv);
    attn_kernel<<<dim3(Bn * Hn, Tn / 64), 256, attn_smem>>>(rel);
    proj_mm<<<dim3(64, 8), 256, GEMM_SMEM>>>(Wp, bp, out);
}

// round 4
// speedup vs baseline: 2.9415x; 1.9570x over previous
#include <cuda_runtime.h>
#include <cuda_bf16.h>
#include <cstdint>

// Problem constants
#define Bn 4
#define Tn 2048
#define Cn 512
#define Hn 8
#define Dn 64
__device__ __constant__ float kScale = 0.04419417382415922f; // 512^-0.5

// ---------------------------------------------------------------------------
// Global scratch (bf16 hi/lo pairs; no allocation allowed)
// ---------------------------------------------------------------------------
#define NX  (Bn*Tn*Cn)        // 4194304
#define NW  (Hn*Cn*Dn)        // 262144 per matrix
#define NR  (Hn*Tn*Dn)        // 1048576
#define NP  (Cn*Cn)           // 262144
#define NQ  (Bn*Hn*Tn*Dn)     // 4194304

__device__ __align__(16) __nv_bfloat16 g_xh[NX],  g_xl[NX];
__device__ __align__(16) __nv_bfloat16 g_wth[3*NW], g_wtl[3*NW];   // [mat][h][d][k]
__device__ __align__(16) __nv_bfloat16 g_relh[NR], g_rell[NR];
__device__ __align__(16) __nv_bfloat16 g_wpth[NP], g_wptl[NP];     // [n][k]
__device__ __align__(16) __nv_bfloat16 g_qh[NQ], g_ql[NQ];
__device__ __align__(16) __nv_bfloat16 g_kh[NQ], g_kl[NQ];
__device__ __align__(16) __nv_bfloat16 g_vh[NQ], g_vl[NQ];
__device__ __align__(16) __nv_bfloat16 g_atth[NX], g_attl[NX];

// ---------------------------------------------------------------------------
// helpers
// ---------------------------------------------------------------------------
__device__ __forceinline__ uint32_t smem_u32(const void* p) {
    uint32_t a;
    asm("{ .reg .u64 t; cvta.to.shared.u64 t, %1; cvt.u32.u64 %0, t; }"
        : "=r"(a) : "l"(p));
    return a;
}

__device__ __forceinline__ void ldmx4(uint32_t* r, uint32_t addr) {
    asm volatile("ldmatrix.sync.aligned.m8n8.x4.shared.b16 {%0,%1,%2,%3}, [%4];"
                 : "=r"(r[0]), "=r"(r[1]), "=r"(r[2]), "=r"(r[3]) : "r"(addr));
}
__device__ __forceinline__ void ldmx4t(uint32_t* r, uint32_t addr) {
    asm volatile("ldmatrix.sync.aligned.m8n8.x4.trans.shared.b16 {%0,%1,%2,%3}, [%4];"
                 : "=r"(r[0]), "=r"(r[1]), "=r"(r[2]), "=r"(r[3]) : "r"(addr));
}

__device__ __forceinline__ void mma16816(float* c, const uint32_t* a,
                                         uint32_t b0, uint32_t b1) {
    asm volatile(
        "mma.sync.aligned.m16n8k16.row.col.f32.bf16.bf16.f32 "
        "{%0,%1,%2,%3}, {%4,%5,%6,%7}, {%8,%9}, {%0,%1,%2,%3};"
        : "+f"(c[0]), "+f"(c[1]), "+f"(c[2]), "+f"(c[3])
        : "r"(a[0]), "r"(a[1]), "r"(a[2]), "r"(a[3]), "r"(b0), "r"(b1));
}

// Split fp32 pair into bf16 hi/lo pairs (packed bf16x2; elem0 = x0).
__device__ __forceinline__ void split2(float x0, float x1, uint32_t& hi2, uint32_t& lo2) {
    asm("cvt.rn.bf16x2.f32 %0, %1, %2;" : "=r"(hi2) : "f"(x1), "f"(x0));
    float h0 = __uint_as_float(hi2 << 16);
    float h1 = __uint_as_float(hi2 & 0xFFFF0000u);
    float l0 = x0 - h0, l1 = x1 - h1;
    asm("cvt.rn.bf16x2.f32 %0, %1, %2;" : "=r"(lo2) : "f"(l1), "f"(l0));
}

// bf16 smem tiles padded to 72 elems = 144B rows (9 x 16B phases, conflict-free)
#define LDT 144

// ---------------------------------------------------------------------------
// Pre-split kernels
// ---------------------------------------------------------------------------
__global__ void split_f32(const float* __restrict__ src,
                          __nv_bfloat16* __restrict__ hi,
                          __nv_bfloat16* __restrict__ lo, int n4)
{
    int i = blockIdx.x * blockDim.x + threadIdx.x;
    if (i >= n4) return;
    float4 v = reinterpret_cast<const float4*>(src)[i];
    uint32_t ha, la, hb, lb;
    split2(v.x, v.y, ha, la);
    split2(v.z, v.w, hb, lb);
    reinterpret_cast<uint2*>(hi)[i] = make_uint2(ha, hb);
    reinterpret_cast<uint2*>(lo)[i] = make_uint2(la, lb);
}

// Transposed split: src[b][r][c] -> dst[b][c][r]
__global__ void split_tr(const float* __restrict__ src,
                         __nv_bfloat16* __restrict__ hi,
                         __nv_bfloat16* __restrict__ lo, int rows, int cols)
{
    int b = blockIdx.y;
    int i = blockIdx.x * blockDim.x + threadIdx.x;
    if (i >= rows * cols) return;
    int r = i / cols, c = i % cols;
    float w = src[(size_t)b * rows * cols + i];
    __nv_bfloat16 hb = __float2bfloat16(w);
    __nv_bfloat16 lb = __float2bfloat16(w - __bfloat162float(hb));
    size_t o = (size_t)b * rows * cols + (size_t)c * rows + r;
    hi[o] = hb;
    lo[o] = lb;
}

// ---------------------------------------------------------------------------
// GEMM smem layout (qkv / proj): A 128x64 hi/lo, B 64x64 hi/lo
// ---------------------------------------------------------------------------
#define OFF_AH 0
#define OFF_AL 18432
#define OFF_BH 36864
#define OFF_BL 46080
#define GEMM_SMEM 55296

// ---------------------------------------------------------------------------
// Kernel 1: fused QKV projection on mma.sync.
// grid = (64 m-tiles of 128, 24 = {q,k,v} x head), 256 threads.
// Epilogue writes split bf16 hi/lo of q/k/v.
// ---------------------------------------------------------------------------
__global__ __launch_bounds__(256) void qkv_mm()
{
    extern __shared__ char smc[];
    const uint32_t smb = smem_u32(smc);
    const int tid = threadIdx.x;
    const int wm  = tid >> 5;
    const int lane = tid & 31;

    const int m0   = blockIdx.x * 128;
    const int wsel = blockIdx.y >> 3;
    const int h    = blockIdx.y & 7;
    const __nv_bfloat16* Wh = g_wth + (size_t)(wsel * 8 + h) * Cn * Dn;
    const __nv_bfloat16* Wl = g_wtl + (size_t)(wsel * 8 + h) * Cn * Dn;
    __nv_bfloat16* outh = (wsel == 0 ? g_qh : (wsel == 1 ? g_kh : g_vh));
    __nv_bfloat16* outl = (wsel == 0 ? g_ql : (wsel == 1 ? g_kl : g_vl));

    float c[8][4] = {};
    const int lr = lane & 15;
    const int lc = (lane >> 4) << 3;

    for (int kb = 0; kb < 8; kb++) {
        const int c0 = kb * 64;
        // A tile: copy 128x64 bf16 hi/lo
        #pragma unroll
        for (int i = 0; i < 4; i++) {
            int u = tid + i * 256;          // 1024 chunks of 8 elems
            int row = u >> 3, g = u & 7;
            size_t src = (size_t)(m0 + row) * Cn + c0 + g * 8;
            uint32_t dst = (uint32_t)(row * LDT + g * 16);
            *reinterpret_cast<uint4*>(smc + OFF_AH + dst) =
                *reinterpret_cast<const uint4*>(g_xh + src);
            *reinterpret_cast<uint4*>(smc + OFF_AL + dst) =
                *reinterpret_cast<const uint4*>(g_xl + src);
        }
        // B tile: Wt[d][k] rows 64, cols c0..c0+63
        #pragma unroll
        for (int i = 0; i < 2; i++) {
            int u = tid + i * 256;          // 512 chunks
            int d = u >> 3, g = u & 7;
            size_t src = (size_t)d * Cn + c0 + g * 8;
            uint32_t dst = (uint32_t)(d * LDT + g * 16);
            *reinterpret_cast<uint4*>(smc + OFF_BH + dst) =
                *reinterpret_cast<const uint4*>(Wh + src);
            *reinterpret_cast<uint4*>(smc + OFF_BL + dst) =
                *reinterpret_cast<const uint4*>(Wl + src);
        }
        __syncthreads();

        #pragma unroll
        for (int ks = 0; ks < 4; ks++) {
            const int k0 = ks * 16;
            uint32_t a_hi[4], a_lo[4];
            uint32_t aoff = (uint32_t)((wm * 16 + lr) * LDT + (k0 + lc) * 2);
            ldmx4(a_hi, smb + OFF_AH + aoff);
            ldmx4(a_lo, smb + OFF_AL + aoff);
            #pragma unroll
            for (int ng = 0; ng < 4; ng++) {
                uint32_t bh[4], bl[4];
                uint32_t boff = (uint32_t)((ng * 16 + lr) * LDT + (k0 + lc) * 2);
                ldmx4(bh, smb + OFF_BH + boff);
                ldmx4(bl, smb + OFF_BL + boff);
                mma16816(c[2*ng],   a_hi, bh[0], bh[2]);
                mma16816(c[2*ng],   a_hi, bl[0], bl[2]);
                mma16816(c[2*ng],   a_lo, bh[0], bh[2]);
                mma16816(c[2*ng+1], a_hi, bh[1], bh[3]);
                mma16816(c[2*ng+1], a_hi, bl[1], bl[3]);
                mma16816(c[2*ng+1], a_lo, bh[1], bh[3]);
            }
        }
        __syncthreads();
    }

    const int gid = lane >> 2, qc = (lane & 3) * 2;
    #pragma unroll
    for (int rr = 0; rr < 2; rr++) {
        int m = m0 + wm * 16 + gid + rr * 8;
        int b = m >> 11, t = m & 2047;
        size_t base = (((size_t)(b * Hn + h)) * Tn + t) * Dn;
        #pragma unroll
        for (int j = 0; j < 8; j++) {
            uint32_t hp, lp;
            split2(c[j][rr*2], c[j][rr*2 + 1], hp, lp);
            size_t e = base + j * 8 + qc;
            *reinterpret_cast<uint32_t*>(outh + e) = hp;
            *reinterpret_cast<uint32_t*>(outl + e) = lp;
        }
    }
}

// ---------------------------------------------------------------------------
// Kernel 3: output projection + bias on mma.sync.
// grid = (64 m-tiles of 128, 8 n-tiles of 64), 256 threads. fp32 out.
// ---------------------------------------------------------------------------
__global__ __launch_bounds__(256) void proj_mm(
    const float* __restrict__ bp, float* __restrict__ outp)
{
    extern __shared__ char smc[];
    const uint32_t smb = smem_u32(smc);
    const int tid = threadIdx.x;
    const int wm  = tid >> 5;
    const int lane = tid & 31;

    const int m0 = blockIdx.x * 128;
    const int n0 = blockIdx.y * 64;

    float c[8][4] = {};
    const int lr = lane & 15;
    const int lc = (lane >> 4) << 3;

    for (int kb = 0; kb < 8; kb++) {
        const int c0 = kb * 64;
        #pragma unroll
        for (int i = 0; i < 4; i++) {
            int u = tid + i * 256;
            int row = u >> 3, g = u & 7;
            size_t src = (size_t)(m0 + row) * Cn + c0 + g * 8;
            uint32_t dst = (uint32_t)(row * LDT + g * 16);
            *reinterpret_cast<uint4*>(smc + OFF_AH + dst) =
                *reinterpret_cast<const uint4*>(g_atth + src);
            *reinterpret_cast<uint4*>(smc + OFF_AL + dst) =
                *reinterpret_cast<const uint4*>(g_attl + src);
        }
        #pragma unroll
        for (int i = 0; i < 2; i++) {
            int u = tid + i * 256;
            int d = u >> 3, g = u & 7;
            size_t src = (size_t)(n0 + d) * Cn + c0 + g * 8;
            uint32_t dst = (uint32_t)(d * LDT + g * 16);
            *reinterpret_cast<uint4*>(smc + OFF_BH + dst) =
                *reinterpret_cast<const uint4*>(g_wpth + src);
            *reinterpret_cast<uint4*>(smc + OFF_BL + dst) =
                *reinterpret_cast<const uint4*>(g_wptl + src);
        }
        __syncthreads();

        #pragma unroll
        for (int ks = 0; ks < 4; ks++) {
            const int k0 = ks * 16;
            uint32_t a_hi[4], a_lo[4];
            uint32_t aoff = (uint32_t)((wm * 16 + lr) * LDT + (k0 + lc) * 2);
            ldmx4(a_hi, smb + OFF_AH + aoff);
            ldmx4(a_lo, smb + OFF_AL + aoff);
            #pragma unroll
            for (int ng = 0; ng < 4; ng++) {
                uint32_t bh[4], bl[4];
                uint32_t boff = (uint32_t)((ng * 16 + lr) * LDT + (k0 + lc) * 2);
                ldmx4(bh, smb + OFF_BH + boff);
                ldmx4(bl, smb + OFF_BL + boff);
                mma16816(c[2*ng],   a_hi, bh[0], bh[2]);
                mma16816(c[2*ng],   a_hi, bl[0], bl[2]);
                mma16816(c[2*ng],   a_lo, bh[0], bh[2]);
                mma16816(c[2*ng+1], a_hi, bh[1], bh[3]);
                mma16816(c[2*ng+1], a_hi, bl[1], bl[3]);
                mma16816(c[2*ng+1], a_lo, bh[1], bh[3]);
            }
        }
        __syncthreads();
    }

    const int gid = lane >> 2, qc = (lane & 3) * 2;
    #pragma unroll
    for (int rr = 0; rr < 2; rr++) {
        int m = m0 + wm * 16 + gid + rr * 8;
        float* op = outp + (size_t)m * Cn + n0;
        #pragma unroll
        for (int j = 0; j < 8; j++) {
            float2 bv = *reinterpret_cast<const float2*>(bp + n0 + j * 8 + qc);
            *reinterpret_cast<float2*>(op + j * 8 + qc) =
                make_float2(c[j][rr*2] + bv.x, c[j][rr*2 + 1] + bv.y);
        }
    }
}

// ---------------------------------------------------------------------------
// Kernel 2: flash attention on mma.sync (split-bf16, R-reuse).
// grid = (32 bh, 32 q-blocks reversed), 128 threads (4 warps x m16).
// ---------------------------------------------------------------------------
#define A_QH 0
#define A_QL 9216
#define A_KH 18432
#define A_KL 27648
#define A_VH 36864
#define A_VL 46080
#define A_WH 55296
#define A_WL 64512
#define A_R0 73728          // fp32, pitch 66, 16896 B
#define A_R1 90624
#define ATT_SMEM 107520
#define LDR 66

__global__ __launch_bounds__(128) void attn_mm(const float* __restrict__ rel)
{
    extern __shared__ char smc[];
    const uint32_t smb = smem_u32(smc);
    float* Rf = reinterpret_cast<float*>(smc);

    const int tid = threadIdx.x;
    const int wm  = tid >> 5;
    const int lane = tid & 31;
    const int lr = lane & 15;
    const int lc = (lane >> 4) << 3;
    const int gid = lane >> 2, qc = (lane & 3) * 2;

    const int bh = blockIdx.x;
    const int h  = bh & (Hn - 1);
    const int b  = bh >> 3;
    const int t0 = (int)(gridDim.y - 1 - blockIdx.y) * 64;

    const __nv_bfloat16* qgh = g_qh + (size_t)bh * Tn * Dn;
    const __nv_bfloat16* qgl = g_ql + (size_t)bh * Tn * Dn;
    const __nv_bfloat16* kgh = g_kh + (size_t)bh * Tn * Dn;
    const __nv_bfloat16* kgl = g_kl + (size_t)bh * Tn * Dn;
    const __nv_bfloat16* vgh = g_vh + (size_t)bh * Tn * Dn;
    const __nv_bfloat16* vgl = g_vl + (size_t)bh * Tn * Dn;
    const __nv_bfloat16* rgh = g_relh + (size_t)h * Tn * Dn;
    const __nv_bfloat16* rgl = g_rell + (size_t)h * Tn * Dn;
    const float*         relh = rel + (size_t)h * Tn * Dn;

    // ---- load Q tile + first rel window into smem ----
    const int jbase0 = Tn - 64 - t0;
    #pragma unroll
    for (int i = 0; i < 4; i++) {
        int u = tid + i * 128;              // 512 chunks of 8 elems
        int row = u >> 3, g = u & 7;
        uint32_t dst = (uint32_t)(row * LDT + g * 16);
        size_t qs = (size_t)(t0 + row) * Dn + g * 8;
        size_t ws = (size_t)(jbase0 + row) * Dn + g * 8;
        *reinterpret_cast<uint4*>(smc + A_QH + dst) = *reinterpret_cast<const uint4*>(qgh + qs);
        *reinterpret_cast<uint4*>(smc + A_QL + dst) = *reinterpret_cast<const uint4*>(qgl + qs);
        *reinterpret_cast<uint4*>(smc + A_WH + dst) = *reinterpret_cast<const uint4*>(rgh + ws);
        *reinterpret_cast<uint4*>(smc + A_WL + dst) = *reinterpret_cast<const uint4*>(rgl + ws);
    }
    __syncthreads();

    // Q fragments in registers (persist across tiles)
    uint32_t q_hi[4][4], q_lo[4][4];
    #pragma unroll
    for (int ks = 0; ks < 4; ks++) {
        uint32_t aoff = (uint32_t)((wm * 16 + lr) * LDT + (ks * 16 + lc) * 2);
        ldmx4(q_hi[ks], smb + A_QH + aoff);
        ldmx4(q_lo[ks], smb + A_QL + aoff);
    }

    // ---- preload Rprev = Q * RelWin0^T ----
    int rprev = A_R0, rnew = A_R1;
    {
        float c[8][4] = {};
        #pragma unroll
        for (int ks = 0; ks < 4; ks++) {
            #pragma unroll
            for (int ng = 0; ng < 4; ng++) {
                uint32_t bh4[4], bl4[4];
                uint32_t boff = (uint32_t)((ng * 16 + lr) * LDT + (ks * 16 + lc) * 2);
                ldmx4(bh4, smb + A_WH + boff);
                ldmx4(bl4, smb + A_WL + boff);
                mma16816(c[2*ng],   q_hi[ks], bh4[0], bh4[2]);
                mma16816(c[2*ng],   q_hi[ks], bl4[0], bl4[2]);
                mma16816(c[2*ng],   q_lo[ks], bh4[0], bh4[2]);
                mma16816(c[2*ng+1], q_hi[ks], bh4[1], bh4[3]);
                mma16816(c[2*ng+1], q_hi[ks], bl4[1], bl4[3]);
                mma16816(c[2*ng+1], q_lo[ks], bh4[1], bh4[3]);
            }
        }
        float* Rp = Rf + rprev / 4;
        #pragma unroll
        for (int j = 0; j < 8; j++) {
            *reinterpret_cast<float2*>(Rp + (wm*16 + gid)     * LDR + j*8 + qc) =
                make_float2(c[j][0], c[j][1]);
            *reinterpret_cast<float2*>(Rp + (wm*16 + gid + 8) * LDR + j*8 + qc) =
                make_float2(c[j][2], c[j][3]);
        }
        __syncwarp();
    }

    float o[8][4] = {};
    float mrow[2] = {-1e30f, -1e30f};
    float lrow[2] = {};

    for (int s0 = 0; s0 <= t0; s0 += 64) {
        const bool diag = (s0 == t0);
        __syncthreads();

        // load K/V (+ next rel window if !diag)
        #pragma unroll
        for (int i = 0; i < 4; i++) {
            int u = tid + i * 128;
            int row = u >> 3, g = u & 7;
            uint32_t dst = (uint32_t)(row * LDT + g * 16);
            size_t s = (size_t)(s0 + row) * Dn + g * 8;
            *reinterpret_cast<uint4*>(smc + A_KH + dst) = *reinterpret_cast<const uint4*>(kgh + s);
            *reinterpret_cast<uint4*>(smc + A_KL + dst) = *reinterpret_cast<const uint4*>(kgl + s);
            *reinterpret_cast<uint4*>(smc + A_VH + dst) = *reinterpret_cast<const uint4*>(vgh + s);
            *reinterpret_cast<uint4*>(smc + A_VL + dst) = *reinterpret_cast<const uint4*>(vgl + s);
        }
        if (!diag) {
            const int jb = s0 - t0 + Tn;
            #pragma unroll
            for (int i = 0; i < 4; i++) {
                int u = tid + i * 128;
                int row = u >> 3, g = u & 7;
                uint32_t dst = (uint32_t)(row * LDT + g * 16);
                size_t s = (size_t)(jb + row) * Dn + g * 8;
                *reinterpret_cast<uint4*>(smc + A_WH + dst) = *reinterpret_cast<const uint4*>(rgh + s);
                *reinterpret_cast<uint4*>(smc + A_WL + dst) = *reinterpret_cast<const uint4*>(rgl + s);
            }
        }
        __syncthreads();

        float c[8][4];

        // ---- R GEMM (off-diag): Rnew = Q * RelB^T ----
        if (!diag) {
            #pragma unroll
            for (int j = 0; j < 8; j++)
                #pragma unroll
                for (int z = 0; z < 4; z++) c[j][z] = 0.f;
            #pragma unroll
            for (int ks = 0; ks < 4; ks++) {
                #pragma unroll
                for (int ng = 0; ng < 4; ng++) {
                    uint32_t bh4[4], bl4[4];
                    uint32_t boff = (uint32_t)((ng * 16 + lr) * LDT + (ks * 16 + lc) * 2);
                    ldmx4(bh4, smb + A_WH + boff);
                    ldmx4(bl4, smb + A_WL + boff);
                    mma16816(c[2*ng],   q_hi[ks], bh4[0], bh4[2]);
                    mma16816(c[2*ng],   q_hi[ks], bl4[0], bl4[2]);
                    mma16816(c[2*ng],   q_lo[ks], bh4[0], bh4[2]);
                    mma16816(c[2*ng+1], q_hi[ks], bh4[1], bh4[3]);
                    mma16816(c[2*ng+1], q_hi[ks], bl4[1], bl4[3]);
                    mma16816(c[2*ng+1], q_lo[ks], bh4[1], bh4[3]);
                }
            }
            float* Rp = Rf + rnew / 4;
            #pragma unroll
            for (int j = 0; j < 8; j++) {
                *reinterpret_cast<float2*>(Rp + (wm*16 + gid)     * LDR + j*8 + qc) =
                    make_float2(c[j][0], c[j][1]);
                *reinterpret_cast<float2*>(Rp + (wm*16 + gid + 8) * LDR + j*8 + qc) =
                    make_float2(c[j][2], c[j][3]);
            }
            __syncwarp();
        }

        // ---- S GEMM: S = Q * K^T ----
        #pragma unroll
        for (int j = 0; j < 8; j++)
            #pragma unroll
            for (int z = 0; z < 4; z++) c[j][z] = 0.f;
        #pragma unroll
        for (int ks = 0; ks < 4; ks++) {
            #pragma unroll
            for (int ng = 0; ng < 4; ng++) {
                uint32_t bh4[4], bl4[4];
                uint32_t boff = (uint32_t)((ng * 16 + lr) * LDT + (ks * 16 + lc) * 2);
                ldmx4(bh4, smb + A_KH + boff);
                ldmx4(bl4, smb + A_KL + boff);
                mma16816(c[2*ng],   q_hi[ks], bh4[0], bh4[2]);
                mma16816(c[2*ng],   q_hi[ks], bl4[0], bl4[2]);
                mma16816(c[2*ng],   q_lo[ks], bh4[0], bh4[2]);
                mma16816(c[2*ng+1], q_hi[ks], bh4[1], bh4[3]);
                mma16816(c[2*ng+1], q_hi[ks], bl4[1], bl4[3]);
                mma16816(c[2*ng+1], q_lo[ks], bh4[1], bh4[3]);
            }
        }

        // ---- gather BD from Rprev/Rnew ----
        {
            const float* Rp = Rf + rprev / 4;
            const float* Rn = Rf + rnew / 4;
            #pragma unroll
            for (int rr = 0; rr < 2; rr++) {
                int tl = wm*16 + gid + rr*8;
                #pragma unroll
                for (int j = 0; j < 8; j++) {
                    #pragma unroll
                    for (int z = 0; z < 2; z++) {
                        int sl = j*8 + qc + z;
                        int jj = sl - tl + 63;
                        if (jj < 64) c[j][rr*2 + z] += Rp[tl * LDR + jj];
                        else if (!diag) c[j][rr*2 + z] += Rn[tl * LDR + jj - 64];
                    }
                }
            }
        }

        // ---- rel-shift wrap corner (tile 0,0 only) ----
        if (t0 == 0 && s0 == 0 && wm == 0 && gid < 5) {
            int t = gid;
            #pragma unroll
            for (int z = 0; z < 2; z++) {
                int s = qc + z;
                if (s > t + 1 && s < 6) {
                    float bd = 0.f;
                    for (int d = 0; d < 64; d++) {
                        float qv = __bfloat162float(qgh[(t + 1) * Dn + d])
                                 + __bfloat162float(qgl[(t + 1) * Dn + d]);
                        bd += qv * relh[(size_t)(s - t - 2) * Dn + d];
                    }
                    c[0][z] += bd;   // j = 0 covers s < 6 when qc < 6
                }
            }
        }

        // ---- mask + scale + online softmax ----
        #pragma unroll
        for (int rr = 0; rr < 2; rr++) {
            int t = t0 + wm*16 + gid + rr*8;
            float rm = -1e30f;
            #pragma unroll
            for (int j = 0; j < 8; j++) {
                #pragma unroll
                for (int z = 0; z < 2; z++) {
                    int s = s0 + j*8 + qc + z;
                    float v = (s <= t || s < 6) ? c[j][rr*2+z] * kScale : -1e30f;
                    c[j][rr*2+z] = v;
                    rm = fmaxf(rm, v);
                }
            }
            rm = fmaxf(rm, __shfl_xor_sync(0xffffffffu, rm, 1));
            rm = fmaxf(rm, __shfl_xor_sync(0xffffffffu, rm, 2));
            float mnew = fmaxf(mrow[rr], rm);
            float alpha = __expf(mrow[rr] - mnew);
            mrow[rr] = mnew;
            float rs = 0.f;
            #pragma unroll
            for (int j = 0; j < 8; j++) {
                #pragma unroll
                for (int z = 0; z < 2; z++) {
                    float p = __expf(c[j][rr*2+z] - mnew);
                    c[j][rr*2+z] = p;
                    rs += p;
                }
            }
            rs += __shfl_xor_sync(0xffffffffu, rs, 1);
            rs += __shfl_xor_sync(0xffffffffu, rs, 2);
            lrow[rr] = lrow[rr] * alpha + rs;
            #pragma unroll
            for (int j = 0; j < 8; j++) {
                o[j][rr*2]   *= alpha;
                o[j][rr*2+1] *= alpha;
            }
        }

        // ---- P -> split bf16 A-frags (in-register) ----
        uint32_t p_hi[4][4], p_lo[4][4];
        #pragma unroll
        for (int kc = 0; kc < 4; kc++) {
            split2(c[2*kc][0],   c[2*kc][1],   p_hi[kc][0], p_lo[kc][0]);
            split2(c[2*kc][2],   c[2*kc][3],   p_hi[kc][1], p_lo[kc][1]);
            split2(c[2*kc+1][0], c[2*kc+1][1], p_hi[kc][2], p_lo[kc][2]);
            split2(c[2*kc+1][2], c[2*kc+1][3], p_hi[kc][3], p_lo[kc][3]);
        }

        // ---- O += P * V  (V via ldmatrix.trans) ----
        #pragma unroll
        for (int kc = 0; kc < 4; kc++) {
            uint32_t vbase = (uint32_t)(kc*16 + (lane & 7) + ((lane & 16) >> 1)) * LDT;
            #pragma unroll
            for (int ng = 0; ng < 4; ng++) {
                uint32_t bh4[4], bl4[4];
                uint32_t voff = vbase + (uint32_t)(ng*16 + (lane & 8)) * 2;
                ldmx4t(bh4, smb + A_VH + voff);
                ldmx4t(bl4, smb + A_VL + voff);
                mma16816(o[2*ng],   p_hi[kc], bh4[0], bh4[2]);
                mma16816(o[2*ng],   p_hi[kc], bl4[0], bl4[2]);
                mma16816(o[2*ng],   p_lo[kc], bh4[0], bh4[2]);
                mma16816(o[2*ng+1], p_hi[kc], bh4[1], bh4[3]);
                mma16816(o[2*ng+1], p_hi[kc], bl4[1], bl4[3]);
                mma16816(o[2*ng+1], p_lo[kc], bh4[1], bh4[3]);
            }
        }

        if (!diag) { int tp = rprev; rprev = rnew; rnew = tp; }
    }

    // ---- epilogue: att = O / l, split to bf16 hi/lo ----
    #pragma unroll
    for (int rr = 0; rr < 2; rr++) {
        int t = t0 + wm*16 + gid + rr*8;
        float inv = 1.0f / lrow[rr];
        size_t base = ((size_t)b * Tn + t) * Cn + h * Dn;
        #pragma unroll
        for (int j = 0; j < 8; j++) {
            uint32_t hp, lp;
            split2(o[j][rr*2] * inv, o[j][rr*2+1] * inv, hp, lp);
            size_t e = base + j*8 + qc;
            *reinterpret_cast<uint32_t*>(g_atth + e) = hp;
            *reinterpret_cast<uint32_t*>(g_attl + e) = lp;
        }
    }
}

// ---------------------------------------------------------------------------
extern "C" void kernel_launch(void* const* d_in, const int* in_sizes, int n_in,
                              void* d_out, int out_size)
{
    const float* x   = (const float*)d_in[0];
    const float* Wq  = (const float*)d_in[1];
    const float* Wk  = (const float*)d_in[2];
    const float* Wv  = (const float*)d_in[3];
    const float* rel = (const float*)d_in[4];
    const float* Wp  = (const float*)d_in[5];
    const float* bp  = (const float*)d_in[6];
    float* out = (float*)d_out;

    static __nv_bfloat16 *h_xh, *h_xl, *h_wth, *h_wtl, *h_relh, *h_rell,
                         *h_wpth, *h_wptl;
    static bool init = false;
    if (!init) {
        cudaGetSymbolAddress((void**)&h_xh, g_xh);
        cudaGetSymbolAddress((void**)&h_xl, g_xl);
        cudaGetSymbolAddress((void**)&h_wth, g_wth);
        cudaGetSymbolAddress((void**)&h_wtl, g_wtl);
        cudaGetSymbolAddress((void**)&h_relh, g_relh);
        cudaGetSymbolAddress((void**)&h_rell, g_rell);
        cudaGetSymbolAddress((void**)&h_wpth, g_wpth);
        cudaGetSymbolAddress((void**)&h_wptl, g_wptl);
        cudaFuncSetAttribute(qkv_mm,  cudaFuncAttributeMaxDynamicSharedMemorySize, GEMM_SMEM);
        cudaFuncSetAttribute(proj_mm, cudaFuncAttributeMaxDynamicSharedMemorySize, GEMM_SMEM);
        cudaFuncSetAttribute(attn_mm, cudaFuncAttributeMaxDynamicSharedMemorySize, ATT_SMEM);
        init = true;
    }

    // pre-split inputs
    split_f32<<<(NX/4 + 255)/256, 256>>>(x, h_xh, h_xl, NX/4);
    split_f32<<<(NR/4 + 255)/256, 256>>>(rel, h_relh, h_rell, NR/4);
    split_tr<<<dim3((Cn*Dn + 255)/256, Hn), 256>>>(Wq, h_wth,        h_wtl,        Cn, Dn);
    split_tr<<<dim3((Cn*Dn + 255)/256, Hn), 256>>>(Wk, h_wth + NW,   h_wtl + NW,   Cn, Dn);
    split_tr<<<dim3((Cn*Dn + 255)/256, Hn), 256>>>(Wv, h_wth + 2*NW, h_wtl + 2*NW, Cn, Dn);
    split_tr<<<dim3((Cn*Cn + 255)/256, 1), 256>>>(Wp, h_wpth, h_wptl, Cn, Cn);

    qkv_mm<<<dim3(64, 24), 256, GEMM_SMEM>>>();
    attn_mm<<<dim3(Bn * Hn, Tn / 64), 128, ATT_SMEM>>>(rel);
    proj_mm<<<dim3(64, 8), 256, GEMM_SMEM>>>(bp, out);
}